// round 3
// baseline (speedup 1.0000x reference)
#include <cuda_runtime.h>

#define LSEQ 256
#define CIN  8
#define COUT 8
#define HID  32

// Scratch: K[o][d][c], 16-byte aligned for float4 access
__device__ __align__(16) float g_K[COUT * LSEQ * CIN];

// ---------------------------------------------------------------------------
// Kernel 1: SIREN kernel-net at the 16384 distinct (o, d, c) points.
// dt = t[j]-t[i] = -d/L on the causal region. 128 blocks x 128 threads
// (1 warp per SMSP across 128 SMs), __sinf fast path, k-unroll-4 for ILP.
// ---------------------------------------------------------------------------
__global__ __launch_bounds__(128) void kernet_eval(
    const float* __restrict__ v1, const float* __restrict__ g1,
    const float* __restrict__ b1,
    const float* __restrict__ v2, const float* __restrict__ g2,
    const float* __restrict__ b2,
    const float* __restrict__ w3, const float* __restrict__ b3)
{
    __shared__ float  sW1[HID][3];
    __shared__ float  sb1[HID];
    __shared__ float4 sW2[HID][HID / 4];
    __shared__ float  sb2[HID];
    __shared__ float  sw3[HID];
    __shared__ float  sinv2[HID];

    int tid = threadIdx.x;

    if (tid < HID) {
        float a = v1[tid * 3 + 0];
        float b = v1[tid * 3 + 1];
        float c = v1[tid * 3 + 2];
        float inv = g1[tid] * rsqrtf(a * a + b * b + c * c);
        sW1[tid][0] = a * inv;
        sW1[tid][1] = b * inv;
        sW1[tid][2] = c * inv;
        sb1[tid] = b1[tid];
        sb2[tid] = b2[tid];
        sw3[tid] = w3[tid];
        float s = 0.f;
        #pragma unroll
        for (int h = 0; h < HID; h++) {
            float w = v2[tid * HID + h];
            s += w * w;
        }
        sinv2[tid] = g2[tid] * rsqrtf(s);
    }
    __syncthreads();

    #pragma unroll
    for (int e = tid; e < HID * HID; e += 128) {
        int row = e >> 5;
        ((float*)sW2)[e] = v2[e] * sinv2[row];
    }
    __syncthreads();

    // gid = o*2048 + d*8 + c  (g_K laid out [o][d][c])
    int gid = blockIdx.x * 128 + tid;
    int c = gid & 7;
    int d = (gid >> 3) & 255;
    int o = gid >> 11;

    float dt = -(float)d * (1.0f / 256.0f);
    float fc = (float)c;
    float fo = (float)o;

    float h1[HID];
    #pragma unroll
    for (int h = 0; h < HID; h++) {
        float z = fmaf(dt, sW1[h][0], fmaf(fc, sW1[h][1], fmaf(fo, sW1[h][2], sb1[h])));
        h1[h] = __sinf(z);  // OMEGA = 1
    }

    float acc = b3[0];
    #pragma unroll 4
    for (int k = 0; k < HID; k++) {
        float z = sb2[k];
        #pragma unroll
        for (int q = 0; q < HID / 4; q++) {
            float4 w = sW2[k][q];
            z = fmaf(h1[q * 4 + 0], w.x, z);
            z = fmaf(h1[q * 4 + 1], w.y, z);
            z = fmaf(h1[q * 4 + 2], w.z, z);
            z = fmaf(h1[q * 4 + 3], w.w, z);
        }
        acc = fmaf(__sinf(z), sw3[k], acc);
    }

    g_K[gid] = acc;
}

// ---------------------------------------------------------------------------
// Kernel 2: causal conv. 128 blocks, each handles i0 = 2*blockIdx and i0+1.
// 8 warps per block, warp = out-channel o. Lane l handles taps
// d = l + 32*it for it in [0,8) -- FULLY UNROLLED so all loads issue
// up front (MLP ~48), invalid taps masked by multiply.
// ---------------------------------------------------------------------------
__global__ __launch_bounds__(256) void causal_conv(
    const float* __restrict__ x, float* __restrict__ out)
{
    int i1 = blockIdx.x * 2 + 1;     // second position of the pair
    int i0 = i1 - 1;
    int o = threadIdx.x >> 5;
    int l = threadIdx.x & 31;

    const float4* x4 = (const float4*)x;                    // x[j][c]: 2 float4/row
    const float4* k4 = ((const float4*)g_K) + o * (LSEQ * CIN / 4);

    float acc0 = 0.f, acc1 = 0.f;
    #pragma unroll
    for (int it = 0; it < 8; it++) {
        int d = l + 32 * it;                 // always in [0,255]: K load valid
        float4 k0 = __ldg(k4 + 2 * d);
        float4 k1 = __ldg(k4 + 2 * d + 1);

        int j1 = i1 - d;                     // x row for i1
        int j0 = j1 - 1;                     // x row for i0
        bool v1 = (d <= i1);
        bool v0 = (d <= i0);
        int jc1 = v1 ? j1 : 0;
        int jc0 = v0 ? j0 : 0;
        float m1 = v1 ? 1.f : 0.f;
        float m0 = v0 ? 1.f : 0.f;

        float4 a0 = __ldg(x4 + 2 * jc0);
        float4 b0 = __ldg(x4 + 2 * jc0 + 1);
        float4 a1 = __ldg(x4 + 2 * jc1);
        float4 b1 = __ldg(x4 + 2 * jc1 + 1);

        float t0 = k0.x * a0.x;
        t0 = fmaf(k0.y, a0.y, t0);
        t0 = fmaf(k0.z, a0.z, t0);
        t0 = fmaf(k0.w, a0.w, t0);
        t0 = fmaf(k1.x, b0.x, t0);
        t0 = fmaf(k1.y, b0.y, t0);
        t0 = fmaf(k1.z, b0.z, t0);
        t0 = fmaf(k1.w, b0.w, t0);
        acc0 = fmaf(m0, t0, acc0);

        float t1 = k0.x * a1.x;
        t1 = fmaf(k0.y, a1.y, t1);
        t1 = fmaf(k0.z, a1.z, t1);
        t1 = fmaf(k0.w, a1.w, t1);
        t1 = fmaf(k1.x, b1.x, t1);
        t1 = fmaf(k1.y, b1.y, t1);
        t1 = fmaf(k1.z, b1.z, t1);
        t1 = fmaf(k1.w, b1.w, t1);
        acc1 = fmaf(m1, t1, acc1);
    }

    #pragma unroll
    for (int s = 16; s > 0; s >>= 1) {
        acc0 += __shfl_xor_sync(0xFFFFFFFFu, acc0, s);
        acc1 += __shfl_xor_sync(0xFFFFFFFFu, acc1, s);
    }

    if (l == 0) {
        out[i0 * COUT + o] = acc0;
        out[i1 * COUT + o] = acc1;
    }
}

// ---------------------------------------------------------------------------
// Launch. Input order: x, t, v1, g1, b1, v2, g2, b2, w3, b3.
// ---------------------------------------------------------------------------
extern "C" void kernel_launch(void* const* d_in, const int* in_sizes, int n_in,
                              void* d_out, int out_size)
{
    const float* x  = (const float*)d_in[0];
    const float* v1 = (const float*)d_in[2];
    const float* g1 = (const float*)d_in[3];
    const float* b1 = (const float*)d_in[4];
    const float* v2 = (const float*)d_in[5];
    const float* g2 = (const float*)d_in[6];
    const float* b2 = (const float*)d_in[7];
    const float* w3 = (const float*)d_in[8];
    const float* b3 = (const float*)d_in[9];
    float* out = (float*)d_out;

    kernet_eval<<<128, 128>>>(v1, g1, b1, v2, g2, b2, w3, b3);
    causal_conv<<<128, 256>>>(x, out);
}

// round 4
// speedup vs baseline: 1.1946x; 1.1946x over previous
#include <cuda_runtime.h>

#define LSEQ 256
#define CIN  8
#define COUT 8
#define HID  32
#define XPAD 12   // padded row stride (floats) for conflict-free LDS.128

// Scratch: K[o][d][c]
__device__ __align__(16) float g_K[COUT * LSEQ * CIN];

// ---------------------------------------------------------------------------
// Kernel 1: SIREN kernel-net at 16384 (o,d,c) points, split-k x2:
// lanes (2m, 2m+1) share one point. Each lane computes 16 h1 values,
// exchanges via shfl, evaluates 16 output neurons, pair-reduces.
// 128 blocks x 256 threads -> 2 warps/SMSP on 128 SMs.
// ---------------------------------------------------------------------------
__global__ __launch_bounds__(256) void kernet_eval(
    const float* __restrict__ v1, const float* __restrict__ g1,
    const float* __restrict__ b1,
    const float* __restrict__ v2, const float* __restrict__ g2,
    const float* __restrict__ b2,
    const float* __restrict__ w3, const float* __restrict__ b3)
{
    __shared__ float  sW1[HID][3];
    __shared__ float  sb1[HID];
    __shared__ float4 sW2[HID][HID / 4];
    __shared__ float  sb2[HID];
    __shared__ float  sw3[HID];
    __shared__ float  sinv2[HID];

    int tid = threadIdx.x;

    // ---- W2 row norms, cooperatively: thread t owns float4 #t of v2 ----
    float4 w4 = ((const float4*)v2)[tid];          // 256 float4 = all of v2
    float ss = w4.x * w4.x + w4.y * w4.y + w4.z * w4.z + w4.w * w4.w;
    ss += __shfl_xor_sync(0xFFFFFFFFu, ss, 1);
    ss += __shfl_xor_sync(0xFFFFFFFFu, ss, 2);
    ss += __shfl_xor_sync(0xFFFFFFFFu, ss, 4);     // sum over the 8 lanes of a row
    int row = tid >> 3;
    if ((tid & 7) == 0)
        sinv2[row] = g2[row] * rsqrtf(ss);

    if (tid < HID) {
        float a = v1[tid * 3 + 0];
        float b = v1[tid * 3 + 1];
        float c = v1[tid * 3 + 2];
        float inv1 = g1[tid] * rsqrtf(a * a + b * b + c * c);
        sW1[tid][0] = a * inv1;
        sW1[tid][1] = b * inv1;
        sW1[tid][2] = c * inv1;
        sb1[tid] = b1[tid];
        sb2[tid] = b2[tid];
        sw3[tid] = w3[tid];
    }
    __syncthreads();

    float inv = sinv2[row];
    float4 nw;
    nw.x = w4.x * inv; nw.y = w4.y * inv; nw.z = w4.z * inv; nw.w = w4.w * inv;
    ((float4*)sW2)[tid] = nw;
    __syncthreads();

    // ---- point eval ----
    int gt  = blockIdx.x * 256 + tid;
    int pid = gt >> 1;
    int half = tid & 1;                 // pair = adjacent lanes
    int c = pid & 7;
    int d = (pid >> 3) & 255;
    int o = pid >> 11;

    float dt = -(float)d * (1.0f / 256.0f);
    float fc = (float)c;
    float fo = (float)o;

    int hbase = half << 4;              // my 16 h / k indices start here

    // h1 slots 0..15: my half (h = hbase+m); 16..31: partner half
    float h1[HID];
    #pragma unroll
    for (int m = 0; m < 16; m++) {
        int h = hbase + m;
        float z = fmaf(dt, sW1[h][0], fmaf(fc, sW1[h][1], fmaf(fo, sW1[h][2], sb1[h])));
        h1[m] = __sinf(z);              // OMEGA = 1
    }
    #pragma unroll
    for (int m = 0; m < 16; m++)
        h1[16 + m] = __shfl_xor_sync(0xFFFFFFFFu, h1[m], 1);

    int my4 = half << 2;                // my column-quad base within a W2 row
    int ot4 = my4 ^ 4;                  // partner's column quads

    float acc = 0.f;
    #pragma unroll
    for (int m = 0; m < 16; m++) {
        int k = hbase + m;
        const float4* rw = &sW2[k][0];
        float z = sb2[k];
        #pragma unroll
        for (int q = 0; q < 4; q++) {   // my columns <-> h1[0..15]
            float4 w = rw[my4 + q];
            z = fmaf(h1[4*q+0], w.x, z);
            z = fmaf(h1[4*q+1], w.y, z);
            z = fmaf(h1[4*q+2], w.z, z);
            z = fmaf(h1[4*q+3], w.w, z);
        }
        #pragma unroll
        for (int q = 0; q < 4; q++) {   // partner columns <-> h1[16..31]
            float4 w = rw[ot4 + q];
            z = fmaf(h1[16+4*q+0], w.x, z);
            z = fmaf(h1[16+4*q+1], w.y, z);
            z = fmaf(h1[16+4*q+2], w.z, z);
            z = fmaf(h1[16+4*q+3], w.w, z);
        }
        acc = fmaf(__sinf(z), sw3[k], acc);
    }
    acc += __shfl_xor_sync(0xFFFFFFFFu, acc, 1);
    if (half == 0)
        g_K[pid] = acc + b3[0];
}

// ---------------------------------------------------------------------------
// Kernel 2: causal conv from SHARED memory.
// Grid 128 = 8 o x 16 i-tiles. Block stages K[o] (8KB) + x (8KB) into smem
// (rows padded to 12 floats -> conflict-free LDS.128), then each warp
// computes 2 output positions; lanes split taps d = l + 32*it.
// ---------------------------------------------------------------------------
__global__ __launch_bounds__(256) void causal_conv(
    const float* __restrict__ x, float* __restrict__ out)
{
    __shared__ float sk[LSEQ * XPAD];
    __shared__ float sx[LSEQ * XPAD];

    int o    = blockIdx.x >> 4;
    int base = (blockIdx.x & 15) << 4;
    int tid  = threadIdx.x;

    const float4* k4 = (const float4*)(g_K + o * (LSEQ * CIN));
    const float4* x4 = (const float4*)x;
    #pragma unroll
    for (int f = tid; f < 512; f += 256) {
        int r = f >> 1, hh = (f & 1) << 2;
        *(float4*)&sk[r * XPAD + hh] = k4[f];
        *(float4*)&sx[r * XPAD + hh] = x4[f];
    }
    __syncthreads();

    int w = tid >> 5, l = tid & 31;
    int i0 = base + 2 * w;
    int i1 = i0 + 1;

    float acc0 = 0.f, acc1 = 0.f;
    #pragma unroll
    for (int it = 0; it < 8; it++) {
        if ((it << 5) > i1) break;      // warp-uniform early exit
        int d = l + (it << 5);
        float4 ka = *(const float4*)&sk[d * XPAD];
        float4 kb = *(const float4*)&sk[d * XPAD + 4];

        int j1 = i1 - d;
        bool v0 = d <= i0, v1 = d <= i1;
        int jc0 = v0 ? (j1 - 1) : 0;
        int jc1 = v1 ? j1 : 0;
        float m0 = v0 ? 1.f : 0.f;
        float m1 = v1 ? 1.f : 0.f;

        float4 a0 = *(const float4*)&sx[jc0 * XPAD];
        float4 b0 = *(const float4*)&sx[jc0 * XPAD + 4];
        float4 a1 = *(const float4*)&sx[jc1 * XPAD];
        float4 b1 = *(const float4*)&sx[jc1 * XPAD + 4];

        float t0 = ka.x * a0.x;
        t0 = fmaf(ka.y, a0.y, t0);
        t0 = fmaf(ka.z, a0.z, t0);
        t0 = fmaf(ka.w, a0.w, t0);
        t0 = fmaf(kb.x, b0.x, t0);
        t0 = fmaf(kb.y, b0.y, t0);
        t0 = fmaf(kb.z, b0.z, t0);
        t0 = fmaf(kb.w, b0.w, t0);
        acc0 = fmaf(m0, t0, acc0);

        float t1 = ka.x * a1.x;
        t1 = fmaf(ka.y, a1.y, t1);
        t1 = fmaf(ka.z, a1.z, t1);
        t1 = fmaf(ka.w, a1.w, t1);
        t1 = fmaf(kb.x, b1.x, t1);
        t1 = fmaf(kb.y, b1.y, t1);
        t1 = fmaf(kb.z, b1.z, t1);
        t1 = fmaf(kb.w, b1.w, t1);
        acc1 = fmaf(m1, t1, acc1);
    }

    #pragma unroll
    for (int s = 16; s > 0; s >>= 1) {
        acc0 += __shfl_xor_sync(0xFFFFFFFFu, acc0, s);
        acc1 += __shfl_xor_sync(0xFFFFFFFFu, acc1, s);
    }

    if (l == 0) {
        out[i0 * COUT + o] = acc0;
        out[i1 * COUT + o] = acc1;
    }
}

// ---------------------------------------------------------------------------
// Launch. Input order: x, t, v1, g1, b1, v2, g2, b2, w3, b3.
// t is the uniform grid arange(L)/L; folded analytically into dt = -d/L.
// ---------------------------------------------------------------------------
extern "C" void kernel_launch(void* const* d_in, const int* in_sizes, int n_in,
                              void* d_out, int out_size)
{
    const float* x  = (const float*)d_in[0];
    const float* v1 = (const float*)d_in[2];
    const float* g1 = (const float*)d_in[3];
    const float* b1 = (const float*)d_in[4];
    const float* v2 = (const float*)d_in[5];
    const float* g2 = (const float*)d_in[6];
    const float* b2 = (const float*)d_in[7];
    const float* w3 = (const float*)d_in[8];
    const float* b3 = (const float*)d_in[9];
    float* out = (float*)d_out;

    kernet_eval<<<128, 256>>>(v1, g1, b1, v2, g2, b2, w3, b3);
    causal_conv<<<128, 256>>>(x, out);
}